// round 16
// baseline (speedup 1.0000x reference)
#include <cuda_runtime.h>

#define NB 4
#define NN 32768
#define NE 262144
#define CHV 16
#define CHE 16
#define HID 64
#define CHM 48   // 2*CHV + CHE

typedef unsigned long long u64;

// ---------------- scratch (static device memory; no allocation) ----------------
__device__ float g_agg_a[NB * NN * CHV];   // 8 MB
__device__ float g_agg_b[NB * NN * CHV];   // 8 MB
__device__ int   g_cnt_a[NN];
__device__ int   g_cnt_b[NN];
__device__ float g_inv_a[NN];
__device__ float g_inv_b[NN];

// ---------------- constant-memory: layer-1 weights + biases --------------------
// Symbol access only (R14: pointer params demote LDC to generic LDG).
__constant__ __align__(16) float cEW1[CHM * HID];   // edge W1 (48,64) 12 KB
__constant__ __align__(16) float cEb1[HID];
__constant__ __align__(16) float cEb2[CHM];
__constant__ __align__(16) float cNW1[CHM * HID];   // node W1 (48,64) 12 KB
__constant__ __align__(16) float cNb1[HID];
__constant__ __align__(16) float cNb2[CHV];

// ---------------- helpers ----------------
__device__ __forceinline__ u64 pack2(float lo, float hi) {
    u64 r;
    asm("mov.b64 %0, {%1, %2};" : "=l"(r) : "f"(lo), "f"(hi));
    return r;
}
__device__ __forceinline__ void unpack2(u64 v, float& lo, float& hi) {
    asm("mov.b64 {%0, %1}, %2;" : "=f"(lo), "=f"(hi) : "l"(v));
}
__device__ __forceinline__ u64 fma2(u64 a, u64 b, u64 c) {
    u64 d;
    asm("fma.rn.f32x2 %0, %1, %2, %3;" : "=l"(d) : "l"(a), "l"(b), "l"(c));
    return d;
}
__device__ __forceinline__ float fast_tanh(float x) {
    float y;
    asm("tanh.approx.f32 %0, %1;" : "=f"(y) : "f"(x));
    return y;
}
__device__ __forceinline__ void red_add_v4(float* addr, float x, float y, float z, float w) {
    asm volatile("red.global.add.v4.f32 [%0], {%1, %2, %3, %4};"
                 :: "l"(addr), "f"(x), "f"(y), "f"(z), "f"(w) : "memory");
}

// Layer-1 consume for an edge PAIR: one constant weight load feeds both edges.
template<int I>
__device__ __forceinline__ void consumeE1p(u64* a0, u64* a1, float x0, float x1) {
    u64 h0 = pack2(x0, x0);
    u64 h1 = pack2(x1, x1);
    const ulonglong2* w = (const ulonglong2*)(cEW1 + I * HID);
    #pragma unroll
    for (int q = 0; q < HID / 4; q++) {
        ulonglong2 wv = w[q];
        a0[2 * q + 0] = fma2(h0, wv.x, a0[2 * q + 0]);
        a0[2 * q + 1] = fma2(h0, wv.y, a0[2 * q + 1]);
        a1[2 * q + 0] = fma2(h1, wv.x, a1[2 * q + 0]);
        a1[2 * q + 1] = fma2(h1, wv.y, a1[2 * q + 1]);
    }
}
template<int I0>
__device__ __forceinline__ void consumeE4p(u64* a0, u64* a1, float4 v0, float4 v1) {
    consumeE1p<I0 + 0>(a0, a1, v0.x, v1.x);
    consumeE1p<I0 + 1>(a0, a1, v0.y, v1.y);
    consumeE1p<I0 + 2>(a0, a1, v0.z, v1.z);
    consumeE1p<I0 + 3>(a0, a1, v0.w, v1.w);
}

// Node-kernel layer-1 consume (single item).
template<int I>
__device__ __forceinline__ void consumeN1(u64* acc, float x) {
    u64 hh = pack2(x, x);
    const ulonglong2* w = (const ulonglong2*)(cNW1 + I * HID);
    #pragma unroll
    for (int q = 0; q < HID / 4; q++) {
        ulonglong2 wv = w[q];
        acc[2 * q + 0] = fma2(hh, wv.x, acc[2 * q + 0]);
        acc[2 * q + 1] = fma2(hh, wv.y, acc[2 * q + 1]);
    }
}
template<int I0>
__device__ __forceinline__ void consumeN4(u64* acc, float4 v) {
    consumeN1<I0 + 0>(acc, v.x);
    consumeN1<I0 + 1>(acc, v.y);
    consumeN1<I0 + 2>(acc, v.z);
    consumeN1<I0 + 3>(acc, v.w);
}

// ---------------- setup kernels ----------------
__global__ void zero_kernel() {
    int i = blockIdx.x * blockDim.x + threadIdx.x;
    const int n4 = NB * NN * CHV / 4;
    if (i < n4) {
        ((float4*)g_agg_a)[i] = make_float4(0.f, 0.f, 0.f, 0.f);
        ((float4*)g_agg_b)[i] = make_float4(0.f, 0.f, 0.f, 0.f);
    }
    if (i < NN) { g_cnt_a[i] = 0; g_cnt_b[i] = 0; }
}

__global__ void count_kernel(const int* __restrict__ ca, const int* __restrict__ cb) {
    int e = blockIdx.x * blockDim.x + threadIdx.x;
    if (e < NE) {
        atomicAdd(&g_cnt_a[ca[e]], 1);
        atomicAdd(&g_cnt_b[cb[e]], 1);
    }
}

__global__ void inv_kernel() {
    int n = blockIdx.x * blockDim.x + threadIdx.x;
    if (n < NN) {
        g_inv_a[n] = 1.0f / fmaxf((float)g_cnt_a[n], 1.0f);
        g_inv_b[n] = 1.0f / fmaxf((float)g_cnt_b[n], 1.0f);
    }
}

// ---------------- edge message kernel: TWO edges per thread --------------------
// Edges 2*ep, 2*ep+1 share every weight load. Layer 2 runs in three 16-column
// passes so m-registers stay small and results scatter immediately.
__global__ __launch_bounds__(128, 2) void edge_kernel(
    const float* __restrict__ nv, const float* __restrict__ ev,
    const int* __restrict__ ca, const int* __restrict__ cb,
    const float* __restrict__ W2,
    float* __restrict__ out_edge)
{
    __shared__ __align__(16) float sW2[HID * CHM];   // (64,48) row-major, 12 KB
    for (int i = threadIdx.x; i < HID * CHM; i += 128) sW2[i] = W2[i];
    __syncthreads();

    int g  = blockIdx.x * 128 + threadIdx.x;   // NB*NE/2 threads
    int b  = g >> 17;                          // / (NE/2)
    int ep = g & (NE / 2 - 1);
    int e0 = ep * 2;
    size_t tf = (size_t)b * NE + e0;           // flat index of edge0

    int2 na = *(const int2*)(ca + e0);
    int2 nb = *(const int2*)(cb + e0);

    const float4* pa0 = (const float4*)(nv + ((b << 15) + na.x) * CHV);
    const float4* pa1 = (const float4*)(nv + ((b << 15) + na.y) * CHV);
    const float4* pb0 = (const float4*)(nv + ((b << 15) + nb.x) * CHV);
    const float4* pb1 = (const float4*)(nv + ((b << 15) + nb.y) * CHV);
    const float4* pe  = (const float4*)(ev + tf * CHE);   // edge0: [0..3], edge1: [4..7]

    // ---- layer 1: two accumulator sets, shared weight stream (const port) ----
    u64 acc0[HID / 2], acc1[HID / 2];
    {
        const u64* b1p = (const u64*)cEb1;
        #pragma unroll
        for (int p = 0; p < HID / 2; p++) { acc0[p] = b1p[p]; acc1[p] = b1p[p]; }
    }
    consumeE4p< 0>(acc0, acc1, pa0[0], pa1[0]);
    consumeE4p< 4>(acc0, acc1, pa0[1], pa1[1]);
    consumeE4p< 8>(acc0, acc1, pa0[2], pa1[2]);
    consumeE4p<12>(acc0, acc1, pa0[3], pa1[3]);
    consumeE4p<16>(acc0, acc1, pb0[0], pb1[0]);
    consumeE4p<20>(acc0, acc1, pb0[1], pb1[1]);
    consumeE4p<24>(acc0, acc1, pb0[2], pb1[2]);
    consumeE4p<28>(acc0, acc1, pb0[3], pb1[3]);
    consumeE4p<32>(acc0, acc1, pe[0], pe[4]);
    consumeE4p<36>(acc0, acc1, pe[1], pe[5]);
    consumeE4p<40>(acc0, acc1, pe[2], pe[6]);
    consumeE4p<44>(acc0, acc1, pe[3], pe[7]);

    // ---- tanh in place ----
    #pragma unroll
    for (int p = 0; p < HID / 2; p++) {
        float lo, hi;
        unpack2(acc0[p], lo, hi);
        acc0[p] = pack2(fast_tanh(lo), fast_tanh(hi));
        unpack2(acc1[p], lo, hi);
        acc1[p] = pack2(fast_tanh(lo), fast_tanh(hi));
    }

    // ---- layer 2 in three 16-column passes; scatter each block immediately ----
    float* aga0 = g_agg_a + ((b << 15) + na.x) * CHV;
    float* aga1 = g_agg_a + ((b << 15) + na.y) * CHV;
    float* agb0 = g_agg_b + ((b << 15) + nb.x) * CHV;
    float* agb1 = g_agg_b + ((b << 15) + nb.y) * CHV;
    float4* oe  = (float4*)(out_edge + tf * CHE);

    #pragma unroll
    for (int ko = 0; ko < 3; ko++) {          // output columns [16*ko, 16*ko+16)
        u64 m0[8], m1[8];
        {
            const u64* bb = (const u64*)(cEb2 + 16 * ko);
            #pragma unroll
            for (int k = 0; k < 8; k++) { m0[k] = bb[k]; m1[k] = bb[k]; }
        }
        #pragma unroll
        for (int p = 0; p < HID / 2; p++) {   // rows 2p, 2p+1
            float l0, h0f, l1, h1f;
            unpack2(acc0[p], l0, h0f);
            unpack2(acc1[p], l1, h1f);
            u64 ta0 = pack2(l0, l0),  tb0 = pack2(h0f, h0f);
            u64 ta1 = pack2(l1, l1),  tb1 = pack2(h1f, h1f);
            const ulonglong2* w0 = (const ulonglong2*)(sW2 + (2 * p)     * CHM + 16 * ko);
            const ulonglong2* w1 = (const ulonglong2*)(sW2 + (2 * p + 1) * CHM + 16 * ko);
            #pragma unroll
            for (int q = 0; q < 4; q++) {     // 16 floats = 4 ulonglong2
                ulonglong2 wv = w0[q];
                m0[2 * q + 0] = fma2(ta0, wv.x, m0[2 * q + 0]);
                m0[2 * q + 1] = fma2(ta0, wv.y, m0[2 * q + 1]);
                m1[2 * q + 0] = fma2(ta1, wv.x, m1[2 * q + 0]);
                m1[2 * q + 1] = fma2(ta1, wv.y, m1[2 * q + 1]);
            }
            #pragma unroll
            for (int q = 0; q < 4; q++) {
                ulonglong2 wv = w1[q];
                m0[2 * q + 0] = fma2(tb0, wv.x, m0[2 * q + 0]);
                m0[2 * q + 1] = fma2(tb0, wv.y, m0[2 * q + 1]);
                m1[2 * q + 0] = fma2(tb1, wv.x, m1[2 * q + 0]);
                m1[2 * q + 1] = fma2(tb1, wv.y, m1[2 * q + 1]);
            }
        }
        // unpack this 16-wide block and emit it
        float v0[16], v1[16];
        #pragma unroll
        for (int k = 0; k < 8; k++) {
            unpack2(m0[k], v0[2 * k], v0[2 * k + 1]);
            unpack2(m1[k], v1[2 * k], v1[2 * k + 1]);
        }
        if (ko == 0) {            // m_a -> agg_a
            red_add_v4(aga0 + 0,  v0[0],  v0[1],  v0[2],  v0[3]);
            red_add_v4(aga0 + 4,  v0[4],  v0[5],  v0[6],  v0[7]);
            red_add_v4(aga0 + 8,  v0[8],  v0[9],  v0[10], v0[11]);
            red_add_v4(aga0 + 12, v0[12], v0[13], v0[14], v0[15]);
            red_add_v4(aga1 + 0,  v1[0],  v1[1],  v1[2],  v1[3]);
            red_add_v4(aga1 + 4,  v1[4],  v1[5],  v1[6],  v1[7]);
            red_add_v4(aga1 + 8,  v1[8],  v1[9],  v1[10], v1[11]);
            red_add_v4(aga1 + 12, v1[12], v1[13], v1[14], v1[15]);
        } else if (ko == 1) {     // m_b -> agg_b
            red_add_v4(agb0 + 0,  v0[0],  v0[1],  v0[2],  v0[3]);
            red_add_v4(agb0 + 4,  v0[4],  v0[5],  v0[6],  v0[7]);
            red_add_v4(agb0 + 8,  v0[8],  v0[9],  v0[10], v0[11]);
            red_add_v4(agb0 + 12, v0[12], v0[13], v0[14], v0[15]);
            red_add_v4(agb1 + 0,  v1[0],  v1[1],  v1[2],  v1[3]);
            red_add_v4(agb1 + 4,  v1[4],  v1[5],  v1[6],  v1[7]);
            red_add_v4(agb1 + 8,  v1[8],  v1[9],  v1[10], v1[11]);
            red_add_v4(agb1 + 12, v1[12], v1[13], v1[14], v1[15]);
        } else {                  // m_ab + edge_vals -> out_edge
            #pragma unroll
            for (int q = 0; q < 4; q++) {
                float4 evv = pe[q];
                oe[q] = make_float4(evv.x + v0[4 * q + 0], evv.y + v0[4 * q + 1],
                                    evv.z + v0[4 * q + 2], evv.w + v0[4 * q + 3]);
            }
            #pragma unroll
            for (int q = 0; q < 4; q++) {
                float4 evv = pe[4 + q];
                oe[4 + q] = make_float4(evv.x + v1[4 * q + 0], evv.y + v1[4 * q + 1],
                                        evv.z + v1[4 * q + 2], evv.w + v1[4 * q + 3]);
            }
        }
    }
}

// ---------------- node update kernel (unchanged from R15) ----------------------
__global__ __launch_bounds__(128, 4) void node_kernel(
    const float* __restrict__ nv,
    const float* __restrict__ W2,
    float* __restrict__ out_node)
{
    __shared__ __align__(16) float sW2[HID * CHV];   // (64,16) 4 KB
    for (int i = threadIdx.x; i < HID * CHV; i += 128) sW2[i] = W2[i];
    __syncthreads();

    int t = blockIdx.x * 128 + threadIdx.x;
    int n = t & (NN - 1);

    float inva = g_inv_a[n];
    float invb = g_inv_b[n];

    const float4* pa = (const float4*)(g_agg_a + t * CHV);
    const float4* pb = (const float4*)(g_agg_b + t * CHV);
    const float4* pn = (const float4*)(nv + t * CHV);

    u64 acc[HID / 2];
    {
        const u64* b1p = (const u64*)cNb1;
        #pragma unroll
        for (int p = 0; p < HID / 2; p++) acc[p] = b1p[p];
    }
    {
        float4 v;
        v = pa[0]; v.x *= inva; v.y *= inva; v.z *= inva; v.w *= inva; consumeN4< 0>(acc, v);
        v = pa[1]; v.x *= inva; v.y *= inva; v.z *= inva; v.w *= inva; consumeN4< 4>(acc, v);
        v = pa[2]; v.x *= inva; v.y *= inva; v.z *= inva; v.w *= inva; consumeN4< 8>(acc, v);
        v = pa[3]; v.x *= inva; v.y *= inva; v.z *= inva; v.w *= inva; consumeN4<12>(acc, v);
        v = pb[0]; v.x *= invb; v.y *= invb; v.z *= invb; v.w *= invb; consumeN4<16>(acc, v);
        v = pb[1]; v.x *= invb; v.y *= invb; v.z *= invb; v.w *= invb; consumeN4<20>(acc, v);
        v = pb[2]; v.x *= invb; v.y *= invb; v.z *= invb; v.w *= invb; consumeN4<24>(acc, v);
        v = pb[3]; v.x *= invb; v.y *= invb; v.z *= invb; v.w *= invb; consumeN4<28>(acc, v);
    }
    consumeN4<32>(acc, pn[0]);
    consumeN4<36>(acc, pn[1]);
    consumeN4<40>(acc, pn[2]);
    consumeN4<44>(acc, pn[3]);

    u64 m[CHV / 2];
    {
        const u64* b2p = (const u64*)cNb2;
        #pragma unroll
        for (int p = 0; p < CHV / 2; p++) m[p] = b2p[p];
    }
    #pragma unroll
    for (int p = 0; p < HID / 2; p++) {
        float lo, hi;
        unpack2(acc[p], lo, hi);
        float tl = fast_tanh(lo);
        float th = fast_tanh(hi);
        u64 t0 = pack2(tl, tl);
        u64 t1 = pack2(th, th);
        const ulonglong2* w0 = (const ulonglong2*)(sW2 + (2 * p)     * CHV);
        const ulonglong2* w1 = (const ulonglong2*)(sW2 + (2 * p + 1) * CHV);
        #pragma unroll
        for (int q = 0; q < CHV / 4; q++) {
            ulonglong2 wv0 = w0[q];
            m[2 * q + 0] = fma2(t0, wv0.x, m[2 * q + 0]);
            m[2 * q + 1] = fma2(t0, wv0.y, m[2 * q + 1]);
            ulonglong2 wv1 = w1[q];
            m[2 * q + 0] = fma2(t1, wv1.x, m[2 * q + 0]);
            m[2 * q + 1] = fma2(t1, wv1.y, m[2 * q + 1]);
        }
    }

    float upd[CHV];
    #pragma unroll
    for (int p = 0; p < CHV / 2; p++) unpack2(m[p], upd[2 * p], upd[2 * p + 1]);

    {
        float4* on = (float4*)(out_node + t * CHV);
        #pragma unroll
        for (int q = 0; q < 4; q++) {
            float4 v = pn[q];
            on[q] = make_float4(v.x + upd[4 * q + 0], v.y + upd[4 * q + 1],
                                v.z + upd[4 * q + 2], v.w + upd[4 * q + 3]);
        }
    }
}

// ---------------- launch ----------------
extern "C" void kernel_launch(void* const* d_in, const int* in_sizes, int n_in,
                              void* d_out, int out_size) {
    const float* nv  = (const float*)d_in[0];
    const float* ev  = (const float*)d_in[1];
    const int*   ca  = (const int*)  d_in[2];
    const int*   cb  = (const int*)  d_in[3];
    const float* Wm1 = (const float*)d_in[4];
    const float* bm1 = (const float*)d_in[5];
    const float* Wm2 = (const float*)d_in[6];
    const float* bm2 = (const float*)d_in[7];
    const float* Wu1 = (const float*)d_in[8];
    const float* bu1 = (const float*)d_in[9];
    const float* Wu2 = (const float*)d_in[10];
    const float* bu2 = (const float*)d_in[11];

    float* out      = (float*)d_out;
    float* out_node = out;                       // (B, NN, CHV) first
    float* out_edge = out + NB * NN * CHV;       // (B, NE, CHE) second

    cudaMemcpyToSymbolAsync(cEW1, Wm1, CHM * HID * sizeof(float), 0, cudaMemcpyDeviceToDevice, 0);
    cudaMemcpyToSymbolAsync(cEb1, bm1, HID * sizeof(float),       0, cudaMemcpyDeviceToDevice, 0);
    cudaMemcpyToSymbolAsync(cEb2, bm2, CHM * sizeof(float),       0, cudaMemcpyDeviceToDevice, 0);
    cudaMemcpyToSymbolAsync(cNW1, Wu1, CHM * HID * sizeof(float), 0, cudaMemcpyDeviceToDevice, 0);
    cudaMemcpyToSymbolAsync(cNb1, bu1, HID * sizeof(float),       0, cudaMemcpyDeviceToDevice, 0);
    cudaMemcpyToSymbolAsync(cNb2, bu2, CHV * sizeof(float),       0, cudaMemcpyDeviceToDevice, 0);

    zero_kernel <<< (NB * NN * CHV / 4 + 255) / 256, 256 >>> ();
    count_kernel<<< NE / 256, 256 >>> (ca, cb);
    inv_kernel  <<< NN / 256, 256 >>> ();
    edge_kernel <<< NB * NE / 2 / 128, 128 >>> (nv, ev, ca, cb, Wm2, out_edge);
    node_kernel <<< NB * NN / 128, 128 >>> (nv, Wu2, out_node);
}

// round 17
// speedup vs baseline: 1.0784x; 1.0784x over previous
#include <cuda_runtime.h>

#define NB 4
#define NN 32768
#define NE 262144
#define CHV 16
#define CHE 16
#define HID 64
#define CHM 48   // 2*CHV + CHE
#define W1_CONST_ROWS 36   // W1 rows 0..35 via const port, 36..47 via SMEM

typedef unsigned long long u64;

// ---------------- scratch (static device memory; no allocation) ----------------
__device__ float g_agg_a[NB * NN * CHV];   // 8 MB
__device__ float g_agg_b[NB * NN * CHV];   // 8 MB
__device__ int   g_cnt_a[NN];
__device__ int   g_cnt_b[NN];
__device__ float g_inv_a[NN];
__device__ float g_inv_b[NN];

// ---------------- constant-memory weights --------------------------------------
// Symbol access ONLY with compile-time offsets (R14: pointer params demote to LDG).
__constant__ __align__(16) float cEW1[CHM * HID];   // edge W1 (48,64); rows 0..35 used via LDC
__constant__ __align__(16) float cEb1[HID];
__constant__ __align__(16) float cEb2[CHM];
__constant__ __align__(16) float cNW1[CHM * HID];   // node W1 (48,64)
__constant__ __align__(16) float cNb1[HID];
__constant__ __align__(16) float cNb2[CHV];

// ---------------- helpers ----------------
__device__ __forceinline__ u64 pack2(float lo, float hi) {
    u64 r;
    asm("mov.b64 %0, {%1, %2};" : "=l"(r) : "f"(lo), "f"(hi));
    return r;
}
__device__ __forceinline__ void unpack2(u64 v, float& lo, float& hi) {
    asm("mov.b64 {%0, %1}, %2;" : "=f"(lo), "=f"(hi) : "l"(v));
}
__device__ __forceinline__ u64 fma2(u64 a, u64 b, u64 c) {
    u64 d;
    asm("fma.rn.f32x2 %0, %1, %2, %3;" : "=l"(d) : "l"(a), "l"(b), "l"(c));
    return d;
}
__device__ __forceinline__ float fast_tanh(float x) {
    float y;
    asm("tanh.approx.f32 %0, %1;" : "=f"(y) : "f"(x));
    return y;
}
__device__ __forceinline__ void red_add_v4(float* addr, float x, float y, float z, float w) {
    asm volatile("red.global.add.v4.f32 [%0], {%1, %2, %3, %4};"
                 :: "l"(addr), "f"(x), "f"(y), "f"(z), "f"(w) : "memory");
}

// Edge layer-1 consume: W1 row I from const port (I < W1_CONST_ROWS) or SMEM.
template<int I>
__device__ __forceinline__ void consumeE1(const float* sW1T, u64* acc, float x) {
    u64 hh = pack2(x, x);
    const ulonglong2* w;
    if constexpr (I < W1_CONST_ROWS)
        w = (const ulonglong2*)(cEW1 + I * HID);
    else
        w = (const ulonglong2*)(sW1T + (I - W1_CONST_ROWS) * HID);
    #pragma unroll
    for (int q = 0; q < HID / 4; q++) {
        ulonglong2 wv = w[q];
        acc[2 * q + 0] = fma2(hh, wv.x, acc[2 * q + 0]);
        acc[2 * q + 1] = fma2(hh, wv.y, acc[2 * q + 1]);
    }
}
template<int I0>
__device__ __forceinline__ void consumeE4(const float* sW1T, u64* acc, float4 v) {
    consumeE1<I0 + 0>(sW1T, acc, v.x);
    consumeE1<I0 + 1>(sW1T, acc, v.y);
    consumeE1<I0 + 2>(sW1T, acc, v.z);
    consumeE1<I0 + 3>(sW1T, acc, v.w);
}

// Node layer-1 consume (all const; node kernel is small and was fine in R15).
template<int I>
__device__ __forceinline__ void consumeN1(u64* acc, float x) {
    u64 hh = pack2(x, x);
    const ulonglong2* w = (const ulonglong2*)(cNW1 + I * HID);
    #pragma unroll
    for (int q = 0; q < HID / 4; q++) {
        ulonglong2 wv = w[q];
        acc[2 * q + 0] = fma2(hh, wv.x, acc[2 * q + 0]);
        acc[2 * q + 1] = fma2(hh, wv.y, acc[2 * q + 1]);
    }
}
template<int I0>
__device__ __forceinline__ void consumeN4(u64* acc, float4 v) {
    consumeN1<I0 + 0>(acc, v.x);
    consumeN1<I0 + 1>(acc, v.y);
    consumeN1<I0 + 2>(acc, v.z);
    consumeN1<I0 + 3>(acc, v.w);
}

// ---------------- setup kernels ----------------
__global__ void zero_kernel() {
    int i = blockIdx.x * blockDim.x + threadIdx.x;
    const int n4 = NB * NN * CHV / 4;
    if (i < n4) {
        ((float4*)g_agg_a)[i] = make_float4(0.f, 0.f, 0.f, 0.f);
        ((float4*)g_agg_b)[i] = make_float4(0.f, 0.f, 0.f, 0.f);
    }
    if (i < NN) { g_cnt_a[i] = 0; g_cnt_b[i] = 0; }
}

__global__ void count_kernel(const int* __restrict__ ca, const int* __restrict__ cb) {
    int e = blockIdx.x * blockDim.x + threadIdx.x;
    if (e < NE) {
        atomicAdd(&g_cnt_a[ca[e]], 1);
        atomicAdd(&g_cnt_b[cb[e]], 1);
    }
}

__global__ void inv_kernel() {
    int n = blockIdx.x * blockDim.x + threadIdx.x;
    if (n < NN) {
        g_inv_a[n] = 1.0f / fmaxf((float)g_cnt_a[n], 1.0f);
        g_inv_b[n] = 1.0f / fmaxf((float)g_cnt_b[n], 1.0f);
    }
}

// ---------------- edge message kernel ----------------
// One thread per (batch, edge), R15 structure. Load-port rebalance:
// W1 rows 0..35 const (576 LDC*8=4608 cyc), W1 rows 36..47 + W2 SMEM
// (~960 LDS*4=~4700 cyc incl gathers) -> both ports below fma (6144).
__global__ __launch_bounds__(128, 4) void edge_kernel(
    const float* __restrict__ nv, const float* __restrict__ ev,
    const int* __restrict__ ca, const int* __restrict__ cb,
    const float* __restrict__ W1tail,   // Wm1 + 36*HID
    const float* __restrict__ W2,
    float* __restrict__ out_edge)
{
    __shared__ __align__(16) float sW1T[(CHM - W1_CONST_ROWS) * HID];  // 12x64, 3 KB
    __shared__ __align__(16) float sW2[HID * CHM];                     // 64x48, 12 KB

    for (int i = threadIdx.x; i < (CHM - W1_CONST_ROWS) * HID; i += 128) sW1T[i] = W1tail[i];
    for (int i = threadIdx.x; i < HID * CHM; i += 128) sW2[i] = W2[i];
    __syncthreads();

    int t = blockIdx.x * 128 + threadIdx.x;   // exactly NB*NE threads
    int b = t >> 18;                          // t / NE
    int e = t & (NE - 1);

    int na = ca[e];
    int nb = cb[e];

    const float4* pa = (const float4*)(nv + ((b << 15) + na) * CHV);
    const float4* pb = (const float4*)(nv + ((b << 15) + nb) * CHV);
    const float4* pe = (const float4*)(ev + (size_t)t * CHE);

    // Layer 1: 32 packed accumulators, inputs consumed on the fly
    u64 acc[HID / 2];
    {
        const u64* b1p = (const u64*)cEb1;
        #pragma unroll
        for (int p = 0; p < HID / 2; p++) acc[p] = b1p[p];
    }
    consumeE4< 0>(sW1T, acc, pa[0]);
    consumeE4< 4>(sW1T, acc, pa[1]);
    consumeE4< 8>(sW1T, acc, pa[2]);
    consumeE4<12>(sW1T, acc, pa[3]);
    consumeE4<16>(sW1T, acc, pb[0]);
    consumeE4<20>(sW1T, acc, pb[1]);
    consumeE4<24>(sW1T, acc, pb[2]);
    consumeE4<28>(sW1T, acc, pb[3]);
    consumeE4<32>(sW1T, acc, pe[0]);
    consumeE4<36>(sW1T, acc, pe[1]);
    consumeE4<40>(sW1T, acc, pe[2]);
    consumeE4<44>(sW1T, acc, pe[3]);

    // Layer 2 (tanh fused): weights from SMEM
    u64 m[CHM / 2];
    {
        const u64* b2p = (const u64*)cEb2;
        #pragma unroll
        for (int p = 0; p < CHM / 2; p++) m[p] = b2p[p];
    }
    #pragma unroll
    for (int p = 0; p < HID / 2; p++) {
        float lo, hi;
        unpack2(acc[p], lo, hi);
        float tl = fast_tanh(lo);
        float th = fast_tanh(hi);
        u64 t0 = pack2(tl, tl);
        u64 t1 = pack2(th, th);
        const ulonglong2* w0 = (const ulonglong2*)(sW2 + (2 * p)     * CHM);
        const ulonglong2* w1 = (const ulonglong2*)(sW2 + (2 * p + 1) * CHM);
        #pragma unroll
        for (int q = 0; q < CHM / 4; q++) {
            ulonglong2 wv0 = w0[q];
            m[2 * q + 0] = fma2(t0, wv0.x, m[2 * q + 0]);
            m[2 * q + 1] = fma2(t0, wv0.y, m[2 * q + 1]);
            ulonglong2 wv1 = w1[q];
            m[2 * q + 0] = fma2(t1, wv1.x, m[2 * q + 0]);
            m[2 * q + 1] = fma2(t1, wv1.y, m[2 * q + 1]);
        }
    }

    float mv[CHM];
    #pragma unroll
    for (int p = 0; p < CHM / 2; p++) unpack2(m[p], mv[2 * p], mv[2 * p + 1]);

    // Scatter m_a, m_b with 16B global reductions
    float* aga = g_agg_a + ((b << 15) + na) * CHV;
    red_add_v4(aga + 0,  mv[0],  mv[1],  mv[2],  mv[3]);
    red_add_v4(aga + 4,  mv[4],  mv[5],  mv[6],  mv[7]);
    red_add_v4(aga + 8,  mv[8],  mv[9],  mv[10], mv[11]);
    red_add_v4(aga + 12, mv[12], mv[13], mv[14], mv[15]);

    float* agb = g_agg_b + ((b << 15) + nb) * CHV;
    red_add_v4(agb + 0,  mv[16], mv[17], mv[18], mv[19]);
    red_add_v4(agb + 4,  mv[20], mv[21], mv[22], mv[23]);
    red_add_v4(agb + 8,  mv[24], mv[25], mv[26], mv[27]);
    red_add_v4(agb + 12, mv[28], mv[29], mv[30], mv[31]);

    // new_edge_vals = edge_vals + m_ab (re-read ev; L1 hit)
    {
        float4* oe = (float4*)(out_edge + (size_t)t * CHE);
        #pragma unroll
        for (int q = 0; q < 4; q++) {
            float4 evv = pe[q];
            oe[q] = make_float4(evv.x + mv[32 + 4 * q],
                                evv.y + mv[33 + 4 * q],
                                evv.z + mv[34 + 4 * q],
                                evv.w + mv[35 + 4 * q]);
        }
    }
}

// ---------------- node update kernel (R15, unchanged) --------------------------
__global__ __launch_bounds__(128, 4) void node_kernel(
    const float* __restrict__ nv,
    const float* __restrict__ W2,
    float* __restrict__ out_node)
{
    __shared__ __align__(16) float sW2[HID * CHV];   // (64,16) 4 KB
    for (int i = threadIdx.x; i < HID * CHV; i += 128) sW2[i] = W2[i];
    __syncthreads();

    int t = blockIdx.x * 128 + threadIdx.x;
    int n = t & (NN - 1);

    float inva = g_inv_a[n];
    float invb = g_inv_b[n];

    const float4* pa = (const float4*)(g_agg_a + t * CHV);
    const float4* pb = (const float4*)(g_agg_b + t * CHV);
    const float4* pn = (const float4*)(nv + t * CHV);

    u64 acc[HID / 2];
    {
        const u64* b1p = (const u64*)cNb1;
        #pragma unroll
        for (int p = 0; p < HID / 2; p++) acc[p] = b1p[p];
    }
    {
        float4 v;
        v = pa[0]; v.x *= inva; v.y *= inva; v.z *= inva; v.w *= inva; consumeN4< 0>(acc, v);
        v = pa[1]; v.x *= inva; v.y *= inva; v.z *= inva; v.w *= inva; consumeN4< 4>(acc, v);
        v = pa[2]; v.x *= inva; v.y *= inva; v.z *= inva; v.w *= inva; consumeN4< 8>(acc, v);
        v = pa[3]; v.x *= inva; v.y *= inva; v.z *= inva; v.w *= inva; consumeN4<12>(acc, v);
        v = pb[0]; v.x *= invb; v.y *= invb; v.z *= invb; v.w *= invb; consumeN4<16>(acc, v);
        v = pb[1]; v.x *= invb; v.y *= invb; v.z *= invb; v.w *= invb; consumeN4<20>(acc, v);
        v = pb[2]; v.x *= invb; v.y *= invb; v.z *= invb; v.w *= invb; consumeN4<24>(acc, v);
        v = pb[3]; v.x *= invb; v.y *= invb; v.z *= invb; v.w *= invb; consumeN4<28>(acc, v);
    }
    consumeN4<32>(acc, pn[0]);
    consumeN4<36>(acc, pn[1]);
    consumeN4<40>(acc, pn[2]);
    consumeN4<44>(acc, pn[3]);

    u64 m[CHV / 2];
    {
        const u64* b2p = (const u64*)cNb2;
        #pragma unroll
        for (int p = 0; p < CHV / 2; p++) m[p] = b2p[p];
    }
    #pragma unroll
    for (int p = 0; p < HID / 2; p++) {
        float lo, hi;
        unpack2(acc[p], lo, hi);
        float tl = fast_tanh(lo);
        float th = fast_tanh(hi);
        u64 t0 = pack2(tl, tl);
        u64 t1 = pack2(th, th);
        const ulonglong2* w0 = (const ulonglong2*)(sW2 + (2 * p)     * CHV);
        const ulonglong2* w1 = (const ulonglong2*)(sW2 + (2 * p + 1) * CHV);
        #pragma unroll
        for (int q = 0; q < CHV / 4; q++) {
            ulonglong2 wv0 = w0[q];
            m[2 * q + 0] = fma2(t0, wv0.x, m[2 * q + 0]);
            m[2 * q + 1] = fma2(t0, wv0.y, m[2 * q + 1]);
            ulonglong2 wv1 = w1[q];
            m[2 * q + 0] = fma2(t1, wv1.x, m[2 * q + 0]);
            m[2 * q + 1] = fma2(t1, wv1.y, m[2 * q + 1]);
        }
    }

    float upd[CHV];
    #pragma unroll
    for (int p = 0; p < CHV / 2; p++) unpack2(m[p], upd[2 * p], upd[2 * p + 1]);

    {
        float4* on = (float4*)(out_node + t * CHV);
        #pragma unroll
        for (int q = 0; q < 4; q++) {
            float4 v = pn[q];
            on[q] = make_float4(v.x + upd[4 * q + 0], v.y + upd[4 * q + 1],
                                v.z + upd[4 * q + 2], v.w + upd[4 * q + 3]);
        }
    }
}

// ---------------- launch ----------------
extern "C" void kernel_launch(void* const* d_in, const int* in_sizes, int n_in,
                              void* d_out, int out_size) {
    const float* nv  = (const float*)d_in[0];
    const float* ev  = (const float*)d_in[1];
    const int*   ca  = (const int*)  d_in[2];
    const int*   cb  = (const int*)  d_in[3];
    const float* Wm1 = (const float*)d_in[4];
    const float* bm1 = (const float*)d_in[5];
    const float* Wm2 = (const float*)d_in[6];
    const float* bm2 = (const float*)d_in[7];
    const float* Wu1 = (const float*)d_in[8];
    const float* bu1 = (const float*)d_in[9];
    const float* Wu2 = (const float*)d_in[10];
    const float* bu2 = (const float*)d_in[11];

    float* out      = (float*)d_out;
    float* out_node = out;                       // (B, NN, CHV) first
    float* out_edge = out + NB * NN * CHV;       // (B, NE, CHE) second

    cudaMemcpyToSymbolAsync(cEW1, Wm1, CHM * HID * sizeof(float), 0, cudaMemcpyDeviceToDevice, 0);
    cudaMemcpyToSymbolAsync(cEb1, bm1, HID * sizeof(float),       0, cudaMemcpyDeviceToDevice, 0);
    cudaMemcpyToSymbolAsync(cEb2, bm2, CHM * sizeof(float),       0, cudaMemcpyDeviceToDevice, 0);
    cudaMemcpyToSymbolAsync(cNW1, Wu1, CHM * HID * sizeof(float), 0, cudaMemcpyDeviceToDevice, 0);
    cudaMemcpyToSymbolAsync(cNb1, bu1, HID * sizeof(float),       0, cudaMemcpyDeviceToDevice, 0);
    cudaMemcpyToSymbolAsync(cNb2, bu2, CHV * sizeof(float),       0, cudaMemcpyDeviceToDevice, 0);

    zero_kernel <<< (NB * NN * CHV / 4 + 255) / 256, 256 >>> ();
    count_kernel<<< NE / 256, 256 >>> (ca, cb);
    inv_kernel  <<< NN / 256, 256 >>> ();
    edge_kernel <<< NB * NE / 128, 128 >>> (nv, ev, ca, cb,
                                            Wm1 + W1_CONST_ROWS * HID, Wm2, out_edge);
    node_kernel <<< NB * NN / 128, 128 >>> (nv, Wu2, out_node);
}